// round 9
// baseline (speedup 1.0000x reference)
#include <cuda_runtime.h>
#include <cstdint>

// x: [16, 64, 128, 128] (B, C, H, W), HX = HY = 64.
// Pass 1: 2048 sequences (b,h), T=128 along w.
// Pass 2: 2048 sequences (b,w), T=128 along h.

using ull = unsigned long long;

__device__ float g_pre[2048 * 128 * 64];   // [seq][t][j]
__device__ float g_mid[2048 * 128 * 64];   // [b][w][j][h]
__device__ float g_WTx[64 * 64];           // Wih_x^T: [c][j]
__device__ float g_WTy[64 * 64];
__device__ ull   g_bsdx[64];               // dup'd bias sums
__device__ ull   g_bsdy[64];

__device__ __forceinline__ ull ffma2(ull a, ull b, ull c) {
    ull d;
    asm("fma.rn.f32x2 %0, %1, %2, %3;" : "=l"(d) : "l"(a), "l"(b), "l"(c));
    return d;
}
__device__ __forceinline__ ull addf2(ull a, ull b) {
    ull d;
    asm("add.rn.f32x2 %0, %1, %2;" : "=l"(d) : "l"(a), "l"(b));
    return d;
}
__device__ __forceinline__ ull dup2(float x) {
    unsigned u = __float_as_uint(x);
    return ((ull)u << 32) | (ull)u;
}
__device__ __forceinline__ float lo_f(ull v) { return __uint_as_float((unsigned)(v & 0xffffffffull)); }
__device__ __forceinline__ float hi_f(ull v) { return __uint_as_float((unsigned)(v >> 32)); }
__device__ __forceinline__ float tanh_fast(float x) {
    float r;
    asm("tanh.approx.f32 %0, %1;" : "=f"(r) : "f"(x));
    return r;
}
__device__ __forceinline__ void cp_async16(uint32_t dst, const void* src) {
    asm volatile("cp.async.cg.shared.global [%0], [%1], 16;" :: "r"(dst), "l"(src));
}
#define CP_COMMIT() asm volatile("cp.async.commit_group;")
#define CP_WAIT(n)  asm volatile("cp.async.wait_group %0;" :: "n"(n))

// ---------------------------------------------------------------------------
// Prep: transposed weight tables + dup'd bias sums.
// ---------------------------------------------------------------------------
__global__ void prep_kernel(const float* __restrict__ Wih_x,
                            const float* __restrict__ Wih_y,
                            const float* __restrict__ bih_x,
                            const float* __restrict__ bhh_x,
                            const float* __restrict__ bih_y,
                            const float* __restrict__ bhh_y) {
    int t = threadIdx.x;
    for (int e = t; e < 4096; e += 256) {
        int c = e >> 6, j = e & 63;
        g_WTx[c * 64 + j] = Wih_x[j * 64 + c];
        g_WTy[c * 64 + j] = Wih_y[j * 64 + c];
    }
    if (t < 64) {
        g_bsdx[t] = dup2(bih_x[t] + bhh_x[t]);
        g_bsdy[t] = dup2(bih_y[t] + bhh_y[t]);
    }
}

// ---------------------------------------------------------------------------
// Projection: pre[row][pos][j] = bias[j] + sum_c in[c][pos] * W[j][c]
// Grid 2048 (one block per row, full 128 positions).
// Smem: input tile [c][pos] 32KB + W^T [c][j] 16KB = 48KB.
// Mapping: pt = tid>>4 (X reads warp-broadcast), jt = tid&15 (W conflict-free).
// ---------------------------------------------------------------------------
template <int MODE>
__global__ __launch_bounds__(256) void proj_kernel(const float* __restrict__ src) {
    __shared__ float in_sh[64][128];   // [c][pos]  32KB
    __shared__ float W_sh[64][64];     // [c][j]    16KB

    int tid = threadIdx.x;
    int row = blockIdx.x;

    const float* base;
    size_t stride_c;
    if (MODE == 0) {
        int b = row >> 7, h = row & 127;
        base = src + (size_t)b * 1048576 + (size_t)h * 128;
        stride_c = 16384;
    } else {
        base = g_mid + (size_t)row * 8192;
        stride_c = 128;
    }

    uint32_t shW = (uint32_t)__cvta_generic_to_shared(&W_sh[0][0]);
    uint32_t shI = (uint32_t)__cvta_generic_to_shared(&in_sh[0][0]);

    // Stage W^T: 1024 granules (4/thread). Input tile: 2048 granules (8/thread).
    {
        const float* WT = (MODE == 0) ? g_WTx : g_WTy;
        #pragma unroll
        for (int i = 0; i < 4; i++) {
            int e = tid + i * 256;               // 0..1023
            cp_async16(shW + e * 16, WT + e * 4);
        }
        #pragma unroll
        for (int i = 0; i < 8; i++) {
            int e = tid + i * 256;               // 0..2047, 32 granules/row
            int c = e >> 5, g4 = e & 31;
            cp_async16(shI + e * 16, base + (size_t)c * stride_c + g4 * 4);
        }
        CP_COMMIT();
        CP_WAIT(0);
        __syncthreads();
    }

    int pt = tid >> 4;    // position group of 8 (broadcast X within half-warp)
    int jt = tid & 15;    // output group of 4 (conflict-free W sweep)

    const ull* bd = ((MODE == 0) ? g_bsdx : g_bsdy) + jt * 4;
    ull a[4][4];          // [pos-pair][output]
    #pragma unroll
    for (int o = 0; o < 4; o++) {
        ull bv = bd[o];
        a[0][o] = bv; a[1][o] = bv; a[2][o] = bv; a[3][o] = bv;
    }

    #pragma unroll 8
    for (int c = 0; c < 64; c++) {
        ulonglong2 X0 = *(const ulonglong2*)&in_sh[c][pt * 8];
        ulonglong2 X1 = *(const ulonglong2*)&in_sh[c][pt * 8 + 4];
        float4 wv = *(const float4*)&W_sh[c][jt * 4];
        ull w0 = dup2(wv.x), w1 = dup2(wv.y), w2 = dup2(wv.z), w3 = dup2(wv.w);
        a[0][0] = ffma2(X0.x, w0, a[0][0]);  a[1][0] = ffma2(X0.y, w0, a[1][0]);
        a[2][0] = ffma2(X1.x, w0, a[2][0]);  a[3][0] = ffma2(X1.y, w0, a[3][0]);
        a[0][1] = ffma2(X0.x, w1, a[0][1]);  a[1][1] = ffma2(X0.y, w1, a[1][1]);
        a[2][1] = ffma2(X1.x, w1, a[2][1]);  a[3][1] = ffma2(X1.y, w1, a[3][1]);
        a[0][2] = ffma2(X0.x, w2, a[0][2]);  a[1][2] = ffma2(X0.y, w2, a[1][2]);
        a[2][2] = ffma2(X1.x, w2, a[2][2]);  a[3][2] = ffma2(X1.y, w2, a[3][2]);
        a[0][3] = ffma2(X0.x, w3, a[0][3]);  a[1][3] = ffma2(X0.y, w3, a[1][3]);
        a[2][3] = ffma2(X1.x, w3, a[2][3]);  a[3][3] = ffma2(X1.y, w3, a[3][3]);
    }

    float* dst = g_pre + (size_t)row * 8192 + (pt * 8) * 64 + jt * 4;
    #pragma unroll
    for (int pp = 0; pp < 4; pp++) {
        float4 o;
        o = make_float4(lo_f(a[pp][0]), lo_f(a[pp][1]), lo_f(a[pp][2]), lo_f(a[pp][3]));
        *(float4*)(dst + (pp * 2 + 0) * 64) = o;
        o = make_float4(hi_f(a[pp][0]), hi_f(a[pp][1]), hi_f(a[pp][2]), hi_f(a[pp][3]));
        *(float4*)(dst + (pp * 2 + 1) * 64) = o;
    }
}

// ---------------------------------------------------------------------------
// Recurrent scan: h_t = tanh(pre_t + Whh @ h_{t-1}).
// 128 threads, 4 sequences per block, 2 sequences per thread (w2 reuse).
// Thread (g = tid>>6, j = tid&63) owns hidden unit j of seqs 2g and 2g+1.
// Output pair is contiguous (adjacent seq index) -> direct STG.64, no remap.
// pre staged via double-buffered cp.async chunks of 16 steps.
// MODE 0: write g_mid[b][w][j][h];  MODE 1: write out[b][j][h][w].
// ---------------------------------------------------------------------------
template <int MODE>
__global__ __launch_bounds__(128, 4) void scan_kernel(const float* __restrict__ Whh,
                                                      float* __restrict__ out) {
    __shared__ float pre_sh[2][4][16][64];   // [buf][seq][tt][j] 32KB
    __shared__ float hbuf[2][4][80];         // [buf][seq][j], pad 80

    int tid = threadIdx.x;
    int g   = tid >> 6;                      // 0..1
    int j   = tid & 63;
    int s0  = blockIdx.x * 4;
    int b   = s0 >> 7;
    int p0  = s0 & 127;

    const float* preg = g_pre + (size_t)s0 * 8192;

    ull w2[32];
    {
        const ull* wr = (const ull*)(Whh + j * 64);
        #pragma unroll
        for (int i = 0; i < 32; i++) w2[i] = wr[i];
    }

    hbuf[0][2 * g + 0][j] = 0.f;
    hbuf[0][2 * g + 1][j] = 0.f;

    uint32_t preb = (uint32_t)__cvta_generic_to_shared(&pre_sh[0][0][0][0]);

    // chunk 0: 4 seqs x 16 steps x 64 = 4096 floats = 1024 granules (8/thread)
    {
        #pragma unroll
        for (int i = 0; i < 8; i++) {
            int e = tid + i * 128;               // 0..1023
            int seq = e >> 8, off = (e & 255) * 4;
            cp_async16(preb + (seq * 1024 + off) * 4,
                       preg + (size_t)seq * 8192 + off);
        }
        CP_COMMIT();
    }

    // Direct store base: pair {seq 2g, 2g+1} is contiguous in the target.
    float* outp;
    if (MODE == 0) {
        outp = g_mid + (size_t)b * 1048576 + (size_t)j * 128 + p0 + 2 * g;   // + t*8192
    } else {
        outp = out + (size_t)b * 1048576 + (size_t)j * 16384 + p0 + 2 * g;   // + t*128
    }

    int cur = 0;
    for (int k = 0; k < 8; k++) {
        __syncthreads();                       // buf (k+1)&1 free to overwrite
        if (k < 7) {
            int bk = (k + 1) & 1;
            #pragma unroll
            for (int i = 0; i < 8; i++) {
                int e = tid + i * 128;
                int seq = e >> 8, off = (e & 255) * 4;
                cp_async16(preb + (bk * 4096 + seq * 1024 + off) * 4,
                           preg + (size_t)seq * 8192 + (k + 1) * 1024 + off);
            }
            CP_COMMIT();
            CP_WAIT(1);                        // chunk k landed
        } else {
            CP_WAIT(0);
        }
        __syncthreads();

        const float* pvA = &pre_sh[k & 1][2 * g + 0][0][j];
        const float* pvB = &pre_sh[k & 1][2 * g + 1][0][j];

        #pragma unroll 2
        for (int tt = 0; tt < 16; tt++) {
            float pa = pvA[tt * 64];
            float pb = pvB[tt * 64];

            const ulonglong2* hA = (const ulonglong2*)hbuf[cur][2 * g + 0];
            const ulonglong2* hB = (const ulonglong2*)hbuf[cur][2 * g + 1];
            ull aA0 = 0, aA1 = 0, aA2 = 0, aA3 = 0;
            ull aB0 = 0, aB1 = 0, aB2 = 0, aB3 = 0;
            #pragma unroll
            for (int i = 0; i < 16; i += 2) {
                ulonglong2 ha = hA[i];
                ulonglong2 hb0 = hB[i];
                aA0 = ffma2(w2[2 * i],     ha.x,  aA0);
                aB0 = ffma2(w2[2 * i],     hb0.x, aB0);
                aA1 = ffma2(w2[2 * i + 1], ha.y,  aA1);
                aB1 = ffma2(w2[2 * i + 1], hb0.y, aB1);
                ulonglong2 ha2 = hA[i + 1];
                ulonglong2 hb2 = hB[i + 1];
                aA2 = ffma2(w2[2 * i + 2], ha2.x, aA2);
                aB2 = ffma2(w2[2 * i + 2], hb2.x, aB2);
                aA3 = ffma2(w2[2 * i + 3], ha2.y, aA3);
                aB3 = ffma2(w2[2 * i + 3], hb2.y, aB3);
            }
            aA0 = addf2(aA0, aA1);  aA2 = addf2(aA2, aA3);  aA0 = addf2(aA0, aA2);
            aB0 = addf2(aB0, aB1);  aB2 = addf2(aB2, aB3);  aB0 = addf2(aB0, aB2);
            float hnA = tanh_fast(pa + lo_f(aA0) + hi_f(aA0));
            float hnB = tanh_fast(pb + lo_f(aB0) + hi_f(aB0));

            int nxt = cur ^ 1;
            hbuf[nxt][2 * g + 0][j] = hnA;
            hbuf[nxt][2 * g + 1][j] = hnB;

            int t = k * 16 + tt;
            float2 v = make_float2(hnA, hnB);
            if (MODE == 0) *(float2*)(outp + (size_t)t * 8192) = v;
            else           *(float2*)(outp + (size_t)t * 128)  = v;

            __syncthreads();
            cur = nxt;
        }
    }
}

// ---------------------------------------------------------------------------
extern "C" void kernel_launch(void* const* d_in, const int* in_sizes, int n_in,
                              void* d_out, int out_size) {
    const float* x     = (const float*)d_in[0];
    const float* Wih_x = (const float*)d_in[1];
    const float* Whh_x = (const float*)d_in[2];
    const float* bih_x = (const float*)d_in[3];
    const float* bhh_x = (const float*)d_in[4];
    const float* Wih_y = (const float*)d_in[5];
    const float* Whh_y = (const float*)d_in[6];
    const float* bih_y = (const float*)d_in[7];
    const float* bhh_y = (const float*)d_in[8];
    float* out = (float*)d_out;

    prep_kernel<<<1, 256>>>(Wih_x, Wih_y, bih_x, bhh_x, bih_y, bhh_y);
    proj_kernel<0><<<2048, 256>>>(x);                 // pre_x
    scan_kernel<0><<<512, 128>>>(Whh_x, nullptr);     // scan w -> g_mid [b][w][j][h]
    proj_kernel<1><<<2048, 256>>>(nullptr);           // pre_y
    scan_kernel<1><<<512, 128>>>(Whh_y, out);         // scan h -> out [b][j][h][w]
}